// round 1
// baseline (speedup 1.0000x reference)
#include <cuda_runtime.h>

// GRU with SEQ=1, h0=0:
//   per layer: gi = W_ih x + b_ih ; r=sigma(gi_r+b_hh_r); z=sigma(gi_z+b_hh_z);
//              n=tanh(gi_n + r*b_hh_n); h=(1-z)*n        (w_hh is NEVER used)
//   then out = h @ fc_w^T + fc_b
//
// One thread per sample. Weights + fused biases staged in dynamic SMEM per CTA.
// x/h live in registers; h round-trips through a per-thread SMEM column to
// avoid dynamic register-array indexing (no local-memory spills).

#define LAYERS 5
#define H      32
#define G      96      // 3*H
#define TPB    256

struct SmemLayout {
    float4 wih[LAYERS * G * 8];  // [l][row][q] rows of 32 floats as 8 x float4
    float4 fcw[H * 8];           // [j][q]
    float  bRZ[LAYERS * 64];     // b_ih + b_hh fused for r (0..31) and z (32..63)
    float  bNi[LAYERS * H];      // b_ih for n gate
    float  bNh[LAYERS * H];      // b_hh for n gate (scaled by r at runtime)
    float  fcb[H];
    float  hbuf[TPB * H];        // hbuf[j*TPB + tid] : per-thread column, conflict-free
};

__device__ __forceinline__ float fast_sigmoid(float v) {
    return __fdividef(1.0f, 1.0f + __expf(-v));
}
__device__ __forceinline__ float fast_tanh(float v) {
    // tanh(v) = 1 - 2/(e^{2v}+1); saturates correctly at +/-inf of the exp
    float t = __expf(2.0f * v);
    return 1.0f - __fdividef(2.0f, t + 1.0f);
}

__global__ void __launch_bounds__(TPB, 2)
gru_seq1_kernel(const float* __restrict__ x,
                const float* __restrict__ w_ih,
                const float* __restrict__ b_ih,
                const float* __restrict__ b_hh,
                const float* __restrict__ fc_w,
                const float* __restrict__ fc_b,
                float* __restrict__ out)
{
    extern __shared__ float4 smem_raw[];
    SmemLayout* S = reinterpret_cast<SmemLayout*>(smem_raw);

    const int tid = threadIdx.x;

    // ---- cooperative stage of weights/biases into SMEM ----
    const float4* wih_g = reinterpret_cast<const float4*>(w_ih);
    for (int i = tid; i < LAYERS * G * 8; i += TPB) S->wih[i] = wih_g[i];
    const float4* fcw_g = reinterpret_cast<const float4*>(fc_w);
    for (int i = tid; i < H * 8; i += TPB) S->fcw[i] = fcw_g[i];
    for (int i = tid; i < LAYERS * G; i += TPB) {
        int l = i / G, r = i % G;
        float bi = b_ih[i], bh = b_hh[i];
        if (r < 64) {
            S->bRZ[l * 64 + r] = bi + bh;         // r and z gates: biases fuse
        } else {
            S->bNi[l * H + (r - 64)] = bi;        // n gate: keep separate
            S->bNh[l * H + (r - 64)] = bh;
        }
    }
    for (int i = tid; i < H; i += TPB) S->fcb[i] = fc_b[i];
    __syncthreads();

    // ---- load this thread's sample (32 floats) into registers ----
    const long sample = (long)blockIdx.x * TPB + tid;
    const float4* xg = reinterpret_cast<const float4*>(x + sample * 32);
    float xv[32];
#pragma unroll
    for (int q = 0; q < 8; q++) {
        float4 v = xg[q];
        xv[4*q+0] = v.x; xv[4*q+1] = v.y; xv[4*q+2] = v.z; xv[4*q+3] = v.w;
    }

    // ---- 5 GRU layers ----
#pragma unroll 1
    for (int l = 0; l < LAYERS; l++) {
        const float4* wl = &S->wih[l * G * 8];
#pragma unroll 2
        for (int j = 0; j < H; j++) {
            const float4* wr = wl + j * 8;
            const float4* wz = wl + (j + 32) * 8;
            const float4* wn = wl + (j + 64) * 8;
            float ar = 0.f, az = 0.f, an = 0.f;
#pragma unroll
            for (int q = 0; q < 8; q++) {
                float4 a = wr[q], b = wz[q], c = wn[q];
                ar += a.x * xv[4*q+0]; az += b.x * xv[4*q+0]; an += c.x * xv[4*q+0];
                ar += a.y * xv[4*q+1]; az += b.y * xv[4*q+1]; an += c.y * xv[4*q+1];
                ar += a.z * xv[4*q+2]; az += b.z * xv[4*q+2]; an += c.z * xv[4*q+2];
                ar += a.w * xv[4*q+3]; az += b.w * xv[4*q+3]; an += c.w * xv[4*q+3];
            }
            float r = fast_sigmoid(ar + S->bRZ[l * 64 + j]);
            float z = fast_sigmoid(az + S->bRZ[l * 64 + 32 + j]);
            float n = fast_tanh(an + S->bNi[l * H + j] + r * S->bNh[l * H + j]);
            S->hbuf[j * TPB + tid] = (1.0f - z) * n;   // h_new, since h_prev == 0
        }
        // next layer's input (per-thread column; no cross-thread sharing -> no sync)
#pragma unroll
        for (int k = 0; k < H; k++) xv[k] = S->hbuf[k * TPB + tid];
    }

    // ---- FC: out = h @ fc_w^T + fc_b ----
    float4* og = reinterpret_cast<float4*>(out + sample * 32);
#pragma unroll 1
    for (int j = 0; j < H; j += 4) {
        float acc[4];
#pragma unroll
        for (int u = 0; u < 4; u++) {
            const float4* wj = &S->fcw[(j + u) * 8];
            float a = S->fcb[j + u];
#pragma unroll
            for (int q = 0; q < 8; q++) {
                float4 w4 = wj[q];
                a += w4.x * xv[4*q+0] + w4.y * xv[4*q+1]
                   + w4.z * xv[4*q+2] + w4.w * xv[4*q+3];
            }
            acc[u] = a;
        }
        og[j / 4] = make_float4(acc[0], acc[1], acc[2], acc[3]);
    }
}

extern "C" void kernel_launch(void* const* d_in, const int* in_sizes, int n_in,
                              void* d_out, int out_size)
{
    const float* x    = (const float*)d_in[0];
    const float* w_ih = (const float*)d_in[1];
    // d_in[2] = w_hh : provably unused (SEQ=1, h0=0)
    const float* b_ih = (const float*)d_in[3];
    const float* b_hh = (const float*)d_in[4];
    const float* fc_w = (const float*)d_in[5];
    const float* fc_b = (const float*)d_in[6];
    float* out = (float*)d_out;

    const int batch = in_sizes[0] / 32;      // x is (B, 1, 32)
    const size_t smem = sizeof(SmemLayout);  // ~101 KB -> needs opt-in

    cudaFuncSetAttribute(gru_seq1_kernel,
                         cudaFuncAttributeMaxDynamicSharedMemorySize, (int)smem);

    gru_seq1_kernel<<<batch / TPB, TPB, smem>>>(x, w_ih, b_ih, b_hh,
                                                fc_w, fc_b, out);
}

// round 2
// speedup vs baseline: 1.0938x; 1.0938x over previous
#include <cuda_runtime.h>

// GRU, SEQ=1, h0=0 (w_hh unused):
//   gi = W_ih x + b_ih; r=sig(gi_r+b_hh_r); z=sig(gi_z+b_hh_z);
//   n=tanh(gi_n + r*b_hh_n); h=(1-z)*n; out = h@fc_w^T + fc_b
//
// Round 2: 2 samples/thread (weight LDS amortized across samples),
// k-packed fma.rn.f32x2 (FFMA2), register-resident h (no SMEM hbuf).

#define LAYERS 5
#define H      32
#define G      96
#define TPB    128
#define SPT    2

typedef unsigned long long u64;

struct SmemLayout {
    float4 wih[LAYERS * G * 8];  // row = 32 floats = 8 float4 = 8 ull2
    float4 fcw[H * 8];
    float  bRZ[LAYERS * 64];
    float  bNi[LAYERS * H];
    float  bNh[LAYERS * H];
    float  fcb[H];
};

__device__ __forceinline__ void ffma2(u64& d, u64 a, u64 b) {
    asm("fma.rn.f32x2 %0, %1, %2, %0;" : "+l"(d) : "l"(a), "l"(b));
}
__device__ __forceinline__ float hsum2(u64 v) {
    float lo, hi;
    asm("mov.b64 {%0, %1}, %2;" : "=f"(lo), "=f"(hi) : "l"(v));
    return lo + hi;
}
__device__ __forceinline__ u64 pack2(float a, float b) {
    u64 r;
    asm("mov.b64 %0, {%1, %2};" : "=l"(r) : "f"(a), "f"(b));
    return r;
}
__device__ __forceinline__ float fast_sigmoid(float v) {
    return __fdividef(1.0f, 1.0f + __expf(-v));
}
__device__ __forceinline__ float fast_tanh(float v) {
    float t = __expf(2.0f * v);
    return 1.0f - __fdividef(2.0f, t + 1.0f);
}

// One gate dot-product for both samples: row = 8 ull2 (16 b64 weights).
__device__ __forceinline__ void dot2(const ulonglong2* __restrict__ w,
                                     const u64* __restrict__ xA,
                                     const u64* __restrict__ xB,
                                     u64& aA, u64& aB)
{
#pragma unroll
    for (int q = 0; q < 8; q++) {
        ulonglong2 w2 = w[q];
        ffma2(aA, w2.x, xA[2*q]); ffma2(aA, w2.y, xA[2*q+1]);
        ffma2(aB, w2.x, xB[2*q]); ffma2(aB, w2.y, xB[2*q+1]);
    }
}

__global__ void __launch_bounds__(TPB, 3)
gru_seq1_kernel(const float* __restrict__ x,
                const float* __restrict__ w_ih,
                const float* __restrict__ b_ih,
                const float* __restrict__ b_hh,
                const float* __restrict__ fc_w,
                const float* __restrict__ fc_b,
                float* __restrict__ out)
{
    extern __shared__ float4 smem_raw[];
    SmemLayout* S = reinterpret_cast<SmemLayout*>(smem_raw);
    const int tid = threadIdx.x;

    // ---- cooperative weight/bias staging ----
    const float4* wih_g = reinterpret_cast<const float4*>(w_ih);
    for (int i = tid; i < LAYERS * G * 8; i += TPB) S->wih[i] = wih_g[i];
    const float4* fcw_g = reinterpret_cast<const float4*>(fc_w);
    for (int i = tid; i < H * 8; i += TPB) S->fcw[i] = fcw_g[i];
    for (int i = tid; i < LAYERS * G; i += TPB) {
        int l = i / G, r = i % G;
        float bi = b_ih[i], bh = b_hh[i];
        if (r < 64) S->bRZ[l * 64 + r] = bi + bh;
        else { S->bNi[l * H + (r - 64)] = bi; S->bNh[l * H + (r - 64)] = bh; }
    }
    for (int i = tid; i < H; i += TPB) S->fcb[i] = fc_b[i];
    __syncthreads();

    // ---- load 2 samples, k-packed (16 x b64 each) ----
    const long sA = (long)blockIdx.x * (TPB * SPT) + tid;
    const long sB = sA + TPB;
    u64 xA[16], xB[16];
    {
        const ulonglong2* gA = reinterpret_cast<const ulonglong2*>(x + sA * 32);
        const ulonglong2* gB = reinterpret_cast<const ulonglong2*>(x + sB * 32);
#pragma unroll
        for (int q = 0; q < 8; q++) {
            ulonglong2 va = gA[q]; xA[2*q] = va.x; xA[2*q+1] = va.y;
            ulonglong2 vb = gB[q]; xB[2*q] = vb.x; xB[2*q+1] = vb.y;
        }
    }

    // ---- 5 GRU layers ----
#pragma unroll 1
    for (int l = 0; l < LAYERS; l++) {
        const ulonglong2* wl = reinterpret_cast<const ulonglong2*>(&S->wih[l * G * 8]);
        const float* brz = &S->bRZ[l * 64];
        const float* bni = &S->bNi[l * H];
        const float* bnh = &S->bNh[l * H];
        float hA[H], hB[H];
#pragma unroll
        for (int j = 0; j < H; j++) {
            u64 arA = 0, azA = 0, anA = 0, arB = 0, azB = 0, anB = 0;
            dot2(wl + j * 8,        xA, xB, arA, arB);
            dot2(wl + (j + 32) * 8, xA, xB, azA, azB);
            dot2(wl + (j + 64) * 8, xA, xB, anA, anB);
            float brr = brz[j], brzz = brz[32 + j], bi = bni[j], bh = bnh[j];
            float rA = fast_sigmoid(hsum2(arA) + brr);
            float zA = fast_sigmoid(hsum2(azA) + brzz);
            float nA = fast_tanh(hsum2(anA) + bi + rA * bh);
            hA[j] = (1.0f - zA) * nA;
            float rB = fast_sigmoid(hsum2(arB) + brr);
            float zB = fast_sigmoid(hsum2(azB) + brzz);
            float nB = fast_tanh(hsum2(anB) + bi + rB * bh);
            hB[j] = (1.0f - zB) * nB;
        }
#pragma unroll
        for (int k = 0; k < 16; k++) {
            xA[k] = pack2(hA[2*k], hA[2*k+1]);
            xB[k] = pack2(hB[2*k], hB[2*k+1]);
        }
    }

    // ---- FC: out = h @ fc_w^T + fc_b ----
    float4* oA = reinterpret_cast<float4*>(out + sA * 32);
    float4* oB = reinterpret_cast<float4*>(out + sB * 32);
    const ulonglong2* fw = reinterpret_cast<const ulonglong2*>(S->fcw);
#pragma unroll 1
    for (int j = 0; j < H; j += 4) {
        float accA[4], accB[4];
#pragma unroll
        for (int u = 0; u < 4; u++) {
            u64 aA = 0, aB = 0;
            dot2(fw + (j + u) * 8, xA, xB, aA, aB);
            float b = S->fcb[j + u];
            accA[u] = hsum2(aA) + b;
            accB[u] = hsum2(aB) + b;
        }
        oA[j / 4] = make_float4(accA[0], accA[1], accA[2], accA[3]);
        oB[j / 4] = make_float4(accB[0], accB[1], accB[2], accB[3]);
    }
}

extern "C" void kernel_launch(void* const* d_in, const int* in_sizes, int n_in,
                              void* d_out, int out_size)
{
    const float* x    = (const float*)d_in[0];
    const float* w_ih = (const float*)d_in[1];
    // d_in[2] = w_hh : unused (SEQ=1, h0=0)
    const float* b_ih = (const float*)d_in[3];
    const float* b_hh = (const float*)d_in[4];
    const float* fc_w = (const float*)d_in[5];
    const float* fc_b = (const float*)d_in[6];
    float* out = (float*)d_out;

    const int batch = in_sizes[0] / 32;
    const size_t smem = sizeof(SmemLayout);

    cudaFuncSetAttribute(gru_seq1_kernel,
                         cudaFuncAttributeMaxDynamicSharedMemorySize, (int)smem);

    gru_seq1_kernel<<<batch / (TPB * SPT), TPB, smem>>>(x, w_ih, b_ih, b_hh,
                                                        fc_w, fc_b, out);
}

// round 4
// speedup vs baseline: 6.1108x; 5.5869x over previous
#include <cuda_runtime.h>
#include <cuda_fp16.h>
#include <cstdint>

// GRU (SEQ=1, h0=0 => w_hh unused) via warp-level HMMA mma.sync.m16n8k16.
//   gi = W_ih x + b_ih ; r=sig(gi_r+b_hh_r); z=sig(gi_z+b_hh_z);
//   n=tanh(gi_n + r*b_hh_n); h=(1-z)*n; out = h@fc_w^T + fc_b
//
// Fragment chaining: D fragment (rows t/4, cols (t%4)*2) == A fragment (row,k)
// layout, so layer l's activated outputs are packed in-register into layer
// l+1's A operand. Warps are fully independent after weight staging.

#define TPB     256
#define LAYERS  5
#define WSTRIDE 40   // halves per W row (padded: conflict-free LDS banks)

struct Smem {
    __half W[LAYERS * 96 * WSTRIDE];   // 38400 B
    __half FCW[32 * WSTRIDE];          //  2560 B
    float  BRZ[LAYERS * 64];           // 0.5*(b_ih+b_hh), r units 0..31, z 32..63
    float  BNI[LAYERS * 32];
    float  BNH[LAYERS * 32];
    float  FCB[32];
};                                     // ~43.7 KB -> static smem OK

__device__ __forceinline__ uint32_t pack_h2(float lo, float hi) {
    uint32_t r;  // first src -> upper 16 bits
    asm("cvt.rn.f16x2.f32 %0, %1, %2;" : "=r"(r) : "f"(hi), "f"(lo));
    return r;
}
__device__ __forceinline__ float tanh_fast(float x) {
    float y; asm("tanh.approx.f32 %0, %1;" : "=f"(y) : "f"(x)); return y;
}
__device__ __forceinline__ void mma16816(float* d, const uint32_t* a, const uint32_t* b) {
    asm volatile(
        "mma.sync.aligned.m16n8k16.row.col.f32.f16.f16.f32 "
        "{%0,%1,%2,%3}, {%4,%5,%6,%7}, {%8,%9}, {%0,%1,%2,%3};"
        : "+f"(d[0]), "+f"(d[1]), "+f"(d[2]), "+f"(d[3])
        : "r"(a[0]), "r"(a[1]), "r"(a[2]), "r"(a[3]), "r"(b[0]), "r"(b[1]));
}

__global__ void __launch_bounds__(TPB, 2)
gru_hmma_kernel(const float* __restrict__ x,
                const float* __restrict__ w_ih,
                const float* __restrict__ b_ih,
                const float* __restrict__ b_hh,
                const float* __restrict__ fc_w,
                const float* __restrict__ fc_b,
                float* __restrict__ out)
{
    __shared__ Smem S;
    const int tid = threadIdx.x;

    // ---- stage weights fp32->fp16 (rows padded to WSTRIDE) + fused biases ----
    for (int i = tid; i < LAYERS * 96 * 32; i += TPB) {
        int l = i / 3072, row = (i % 3072) >> 5, k = i & 31;
        S.W[(l * 96 + row) * WSTRIDE + k] = __float2half(w_ih[i]);
    }
    for (int i = tid; i < 32 * 32; i += TPB)
        S.FCW[(i >> 5) * WSTRIDE + (i & 31)] = __float2half(fc_w[i]);
    for (int i = tid; i < LAYERS * 96; i += TPB) {
        int l = i / 96, r = i % 96;
        float bi = b_ih[i], bh = b_hh[i];
        if (r < 64) S.BRZ[l * 64 + r] = 0.5f * (bi + bh);
        else { S.BNI[l * 32 + r - 64] = bi; S.BNH[l * 32 + r - 64] = bh; }
    }
    for (int i = tid; i < 32; i += TPB) S.FCB[i] = fc_b[i];
    __syncthreads();

    const int warp = tid >> 5, lane = tid & 31;
    const int qrow = lane >> 2;          // row within 8-row group
    const int c    = (lane & 3) * 2;     // col pair base
    const size_t rowbase = (size_t)blockIdx.x * 256 + warp * 32;

    // ---- A fragments for layer 1, straight from gmem (fp32 -> f16x2) ----
    // A[m][q][0..3]: q = k16 chunk; {0}=row qrow cols c,c+1; {1}=row+8 same;
    //                {2}=row qrow cols c+8,c+9; {3}=row+8 same.
    uint32_t A[2][2][4];
#pragma unroll
    for (int m = 0; m < 2; m++) {
        const size_t r0 = rowbase + m * 16 + qrow;
#pragma unroll
        for (int q = 0; q < 2; q++) {
            const float* p0 = x + r0 * 32 + q * 16 + c;
            const float* p1 = x + (r0 + 8) * 32 + q * 16 + c;
            float2 v00 = *(const float2*)p0;
            float2 v10 = *(const float2*)p1;
            float2 v01 = *(const float2*)(p0 + 8);
            float2 v11 = *(const float2*)(p1 + 8);
            A[m][q][0] = pack_h2(v00.x, v00.y);
            A[m][q][1] = pack_h2(v10.x, v10.y);
            A[m][q][2] = pack_h2(v01.x, v01.y);
            A[m][q][3] = pack_h2(v11.x, v11.y);
        }
    }

    // ---- 5 GRU layers ----
#pragma unroll
    for (int l = 0; l < LAYERS; l++) {
        const __half* Wl = S.W + l * 96 * WSTRIDE;
        uint32_t nA[2][2][4];
#pragma unroll
        for (int j = 0; j < 4; j++) {          // unit group: units j*8+c, +1
            // B fragments for N-tiles j (r), j+4 (z), j+8 (n); col n = tile*8 + lane/4
            uint32_t Br[2][2], Bz[2][2], Bn[2][2];
#pragma unroll
            for (int q = 0; q < 2; q++) {
                const int nr = (j        ) * 8 + qrow;
                const int nz = (j + 4) * 8 + qrow;
                const int nn = (j + 8) * 8 + qrow;
                Br[q][0] = *(const uint32_t*)(Wl + nr * WSTRIDE + q * 16 + c);
                Br[q][1] = *(const uint32_t*)(Wl + nr * WSTRIDE + q * 16 + c + 8);
                Bz[q][0] = *(const uint32_t*)(Wl + nz * WSTRIDE + q * 16 + c);
                Bz[q][1] = *(const uint32_t*)(Wl + nz * WSTRIDE + q * 16 + c + 8);
                Bn[q][0] = *(const uint32_t*)(Wl + nn * WSTRIDE + q * 16 + c);
                Bn[q][1] = *(const uint32_t*)(Wl + nn * WSTRIDE + q * 16 + c + 8);
            }
            const float2 br = *(const float2*)&S.BRZ[l * 64      + j * 8 + c];
            const float2 bz = *(const float2*)&S.BRZ[l * 64 + 32 + j * 8 + c];
            const float2 bi = *(const float2*)&S.BNI[l * 32      + j * 8 + c];
            const float2 bh = *(const float2*)&S.BNH[l * 32      + j * 8 + c];
#pragma unroll
            for (int m = 0; m < 2; m++) {
                float Dr[4] = {0, 0, 0, 0}, Dz[4] = {0, 0, 0, 0}, Dn[4] = {0, 0, 0, 0};
                mma16816(Dr, A[m][0], Br[0]); mma16816(Dr, A[m][1], Br[1]);
                mma16816(Dz, A[m][0], Bz[0]); mma16816(Dz, A[m][1], Bz[1]);
                mma16816(Dn, A[m][0], Bn[0]); mma16816(Dn, A[m][1], Bn[1]);
                float h[4];
#pragma unroll
                for (int e = 0; e < 4; e++) {  // e: 0=(row,c) 1=(row,c+1) 2=(row+8,c) 3=(row+8,c+1)
                    const float bR = (e & 1) ? br.y : br.x;
                    const float bZ = (e & 1) ? bz.y : bz.x;
                    const float bI = (e & 1) ? bi.y : bi.x;
                    const float bH = (e & 1) ? bh.y : bh.x;
                    float r  = fmaf(tanh_fast(fmaf(Dr[e], 0.5f, bR)),  0.5f, 0.5f);
                    float zc = fmaf(tanh_fast(fmaf(Dz[e], 0.5f, bZ)), -0.5f, 0.5f);
                    float nv = tanh_fast(fmaf(r, bH, Dn[e] + bI));
                    h[e] = zc * nv;            // (1-z)*n, since h_prev = 0
                }
                // D -> next-layer A: chunk j>>1, slots (j&1)*2 (row) and +1 (row+8)
                nA[m][j >> 1][(j & 1) * 2    ] = pack_h2(h[0], h[1]);
                nA[m][j >> 1][(j & 1) * 2 + 1] = pack_h2(h[2], h[3]);
            }
        }
#pragma unroll
        for (int m = 0; m < 2; m++)
#pragma unroll
            for (int q = 0; q < 2; q++)
#pragma unroll
                for (int e = 0; e < 4; e++) A[m][q][e] = nA[m][q][e];
    }

    // ---- FC: D[.,32] = H @ fc_w^T + fc_b, streamed straight to gmem ----
#pragma unroll
    for (int jt = 0; jt < 4; jt++) {
        uint32_t Bf[2][2];
#pragma unroll
        for (int q = 0; q < 2; q++) {
            const int n = jt * 8 + qrow;
            Bf[q][0] = *(const uint32_t*)(S.FCW + n * WSTRIDE + q * 16 + c);
            Bf[q][1] = *(const uint32_t*)(S.FCW + n * WSTRIDE + q * 16 + c + 8);
        }
        const float2 fb = *(const float2*)&S.FCB[jt * 8 + c];
#pragma unroll
        for (int m = 0; m < 2; m++) {
            float D[4] = {fb.x, fb.y, fb.x, fb.y};
            mma16816(D, A[m][0], Bf[0]);
            mma16816(D, A[m][1], Bf[1]);
            const size_t r0 = rowbase + m * 16 + qrow;
            *(float2*)&out[r0 * 32       + jt * 8 + c] = make_float2(D[0], D[1]);
            *(float2*)&out[(r0 + 8) * 32 + jt * 8 + c] = make_float2(D[2], D[3]);
        }
    }
}

extern "C" void kernel_launch(void* const* d_in, const int* in_sizes, int n_in,
                              void* d_out, int out_size)
{
    const float* x    = (const float*)d_in[0];
    const float* w_ih = (const float*)d_in[1];
    // d_in[2] = w_hh : unused (SEQ=1, h0=0)
    const float* b_ih = (const float*)d_in[3];
    const float* b_hh = (const float*)d_in[4];
    const float* fc_w = (const float*)d_in[5];
    const float* fc_b = (const float*)d_in[6];
    float* out = (float*)d_out;

    const int batch = in_sizes[0] / 32;   // 1048576
    const int grid  = batch / 256;        // 256 rows per CTA (8 warps x 32)

    gru_hmma_kernel<<<grid, TPB>>>(x, w_ih, b_ih, b_hh, fc_w, fc_b, out);
}

// round 5
// speedup vs baseline: 6.2274x; 1.0191x over previous
#include <cuda_runtime.h>
#include <cuda_fp16.h>
#include <cstdint>

// GRU (SEQ=1, h0=0 => w_hh unused) via warp-level HMMA m16n8k16 fragment
// chaining. Round 5: r/z weights pre-scaled by 0.5 (sigmoid-via-tanh arg),
// bias-initialized accumulators, ldmatrix.x4 B-fragment loads.

#define TPB     256
#define LAYERS  5
#define WSTRIDE 40   // halves per W row (80 B): conflict-free for LDS & LDSM

struct __align__(16) Smem {
    __half W[LAYERS * 96 * WSTRIDE];   // rows 0-63 (r,z) pre-scaled by 0.5
    __half FCW[32 * WSTRIDE];
    float  BRZ[LAYERS * 64];           // 0.5*(b_ih+b_hh) for r (0..31), z (32..63)
    float  BNI[LAYERS * 32];           // b_ih (n gate)
    float  BNH[LAYERS * 32];           // b_hh (n gate)
    float  FCB[32];
};

__device__ __forceinline__ uint32_t pack_h2(float lo, float hi) {
    uint32_t r;  // first src -> upper 16 bits
    asm("cvt.rn.f16x2.f32 %0, %1, %2;" : "=r"(r) : "f"(hi), "f"(lo));
    return r;
}
__device__ __forceinline__ float tanh_fast(float x) {
    float y; asm("tanh.approx.f32 %0, %1;" : "=f"(y) : "f"(x)); return y;
}
__device__ __forceinline__ void mma16816(float* d, const uint32_t* a, const uint32_t* b) {
    asm volatile(
        "mma.sync.aligned.m16n8k16.row.col.f32.f16.f16.f32 "
        "{%0,%1,%2,%3}, {%4,%5,%6,%7}, {%8,%9}, {%0,%1,%2,%3};"
        : "+f"(d[0]), "+f"(d[1]), "+f"(d[2]), "+f"(d[3])
        : "r"(a[0]), "r"(a[1]), "r"(a[2]), "r"(a[3]), "r"(b[0]), "r"(b[1]));
}
// Loads 4 8x8 b16 tiles; reg i = fragment of tile i (thread t: [t/4][(t%4)*2]).
__device__ __forceinline__ void ldsm_x4(uint32_t* r, uint32_t saddr) {
    asm volatile("ldmatrix.sync.aligned.m8n8.x4.shared.b16 {%0,%1,%2,%3}, [%4];"
        : "=r"(r[0]), "=r"(r[1]), "=r"(r[2]), "=r"(r[3]) : "r"(saddr));
}

__global__ void __launch_bounds__(TPB, 2)
gru_hmma_kernel(const float* __restrict__ x,
                const float* __restrict__ w_ih,
                const float* __restrict__ b_ih,
                const float* __restrict__ b_hh,
                const float* __restrict__ fc_w,
                const float* __restrict__ fc_b,
                float* __restrict__ out)
{
    __shared__ Smem S;
    const int tid = threadIdx.x;

    // ---- stage weights (r/z rows scaled 0.5) + fused biases ----
    for (int i = tid; i < LAYERS * 96 * 32; i += TPB) {
        int l = i / 3072, row = (i % 3072) >> 5, k = i & 31;
        float scale = (row < 64) ? 0.5f : 1.0f;
        S.W[(l * 96 + row) * WSTRIDE + k] = __float2half(w_ih[i] * scale);
    }
    for (int i = tid; i < 32 * 32; i += TPB)
        S.FCW[(i >> 5) * WSTRIDE + (i & 31)] = __float2half(fc_w[i]);
    for (int i = tid; i < LAYERS * 96; i += TPB) {
        int l = i / 96, r = i % 96;
        float bi = b_ih[i], bh = b_hh[i];
        if (r < 64) S.BRZ[l * 64 + r] = 0.5f * (bi + bh);
        else { S.BNI[l * 32 + r - 64] = bi; S.BNH[l * 32 + r - 64] = bh; }
    }
    for (int i = tid; i < 32; i += TPB) S.FCB[i] = fc_b[i];
    __syncthreads();

    const int warp = tid >> 5, lane = tid & 31;
    const int qrow = lane >> 2;          // fragment row within 8-row group
    const int c    = (lane & 3) * 2;     // fragment col pair base
    const size_t rowbase = (size_t)blockIdx.x * 256 + warp * 32;

    // per-thread ldmatrix address offset: tile t/8 (q = bit1, s = bit0), row t%8
    const uint32_t lm_off = (uint32_t)((lane & 7) * (WSTRIDE * 2)
                                       + ((lane >> 4) & 1) * 32
                                       + ((lane >> 3) & 1) * 16);
    const uint32_t wbase  = (uint32_t)__cvta_generic_to_shared(S.W)   + lm_off;
    const uint32_t fbase  = (uint32_t)__cvta_generic_to_shared(S.FCW) + lm_off;

    // ---- A fragments for layer 1 from gmem (fp32 -> f16x2) ----
    uint32_t A[2][2][4];
#pragma unroll
    for (int m = 0; m < 2; m++) {
        const size_t r0 = rowbase + m * 16 + qrow;
#pragma unroll
        for (int q = 0; q < 2; q++) {
            const float* p0 = x + r0 * 32 + q * 16 + c;
            const float* p1 = x + (r0 + 8) * 32 + q * 16 + c;
            float2 v00 = *(const float2*)p0;
            float2 v10 = *(const float2*)p1;
            float2 v01 = *(const float2*)(p0 + 8);
            float2 v11 = *(const float2*)(p1 + 8);
            A[m][q][0] = pack_h2(v00.x, v00.y);
            A[m][q][1] = pack_h2(v10.x, v10.y);
            A[m][q][2] = pack_h2(v01.x, v01.y);
            A[m][q][3] = pack_h2(v11.x, v11.y);
        }
    }

    // ---- 5 GRU layers ----
#pragma unroll
    for (int l = 0; l < LAYERS; l++) {
        uint32_t nA[2][2][4];
#pragma unroll
        for (int j = 0; j < 4; j++) {        // unit group: units j*8 + {c, c+1}
            uint32_t Br[4], Bz[4], Bn[4];    // [0,1]=k0-15, [2,3]=k16-31
            const uint32_t la = wbase + (uint32_t)((l * 96 + j * 8) * (WSTRIDE * 2));
            ldsm_x4(Br, la);
            ldsm_x4(Bz, la + 32 * (WSTRIDE * 2));
            ldsm_x4(Bn, la + 64 * (WSTRIDE * 2));

            const float2 br = *(const float2*)&S.BRZ[l * 64      + j * 8 + c];
            const float2 bz = *(const float2*)&S.BRZ[l * 64 + 32 + j * 8 + c];
            const float2 bi = *(const float2*)&S.BNI[l * 32      + j * 8 + c];
            const float2 bh = *(const float2*)&S.BNH[l * 32      + j * 8 + c];
#pragma unroll
            for (int m = 0; m < 2; m++) {
                // bias-initialized accumulators (cols c, c+1 repeat over rows)
                float Dr[4] = {br.x, br.y, br.x, br.y};
                float Dz[4] = {bz.x, bz.y, bz.x, bz.y};
                float Dn[4] = {bi.x, bi.y, bi.x, bi.y};
                mma16816(Dr, A[m][0], Br + 0); mma16816(Dr, A[m][1], Br + 2);
                mma16816(Dz, A[m][0], Bz + 0); mma16816(Dz, A[m][1], Bz + 2);
                mma16816(Dn, A[m][0], Bn + 0); mma16816(Dn, A[m][1], Bn + 2);
                float h[4];
#pragma unroll
                for (int e = 0; e < 4; e++) {
                    const float bH = (e & 1) ? bh.y : bh.x;
                    float r  = fmaf(tanh_fast(Dr[e]),  0.5f, 0.5f);  // sigmoid
                    float zc = fmaf(tanh_fast(Dz[e]), -0.5f, 0.5f);  // 1 - z
                    float nv = tanh_fast(fmaf(r, bH, Dn[e]));
                    h[e] = zc * nv;          // (1-z)*n, h_prev = 0
                }
                nA[m][j >> 1][(j & 1) * 2    ] = pack_h2(h[0], h[1]);
                nA[m][j >> 1][(j & 1) * 2 + 1] = pack_h2(h[2], h[3]);
            }
        }
#pragma unroll
        for (int m = 0; m < 2; m++)
#pragma unroll
            for (int q = 0; q < 2; q++)
#pragma unroll
                for (int e = 0; e < 4; e++) A[m][q][e] = nA[m][q][e];
    }

    // ---- FC: out = H @ fc_w^T + fc_b ----
#pragma unroll
    for (int jt = 0; jt < 4; jt++) {
        uint32_t Bf[4];
        ldsm_x4(Bf, fbase + (uint32_t)(jt * 8 * (WSTRIDE * 2)));
        const float2 fb = *(const float2*)&S.FCB[jt * 8 + c];
#pragma unroll
        for (int m = 0; m < 2; m++) {
            float D[4] = {fb.x, fb.y, fb.x, fb.y};
            mma16816(D, A[m][0], Bf + 0);
            mma16816(D, A[m][1], Bf + 2);
            const size_t r0 = rowbase + m * 16 + qrow;
            *(float2*)&out[r0 * 32       + jt * 8 + c] = make_float2(D[0], D[1]);
            *(float2*)&out[(r0 + 8) * 32 + jt * 8 + c] = make_float2(D[2], D[3]);
        }
    }
}

extern "C" void kernel_launch(void* const* d_in, const int* in_sizes, int n_in,
                              void* d_out, int out_size)
{
    const float* x    = (const float*)d_in[0];
    const float* w_ih = (const float*)d_in[1];
    // d_in[2] = w_hh : unused (SEQ=1, h0=0)
    const float* b_ih = (const float*)d_in[3];
    const float* b_hh = (const float*)d_in[4];
    const float* fc_w = (const float*)d_in[5];
    const float* fc_b = (const float*)d_in[6];
    float* out = (float*)d_out;

    const int batch = in_sizes[0] / 32;   // 1048576
    const int grid  = batch / 256;        // 256 rows per CTA (8 warps x 32)

    gru_hmma_kernel<<<grid, TPB>>>(x, w_ih, b_ih, b_hh, fc_w, fc_b, out);
}

// round 6
// speedup vs baseline: 6.2504x; 1.0037x over previous
#include <cuda_runtime.h>
#include <cuda_fp16.h>
#include <cstdint>

// GRU (SEQ=1, h0=0 => w_hh unused) via warp-level HMMA m16n8k16 fragment
// chaining. Round 6: fp16x2 activation epilogue (tanh.approx.f16x2 halves
// MUFU; HFMA2 gate math; h2 result IS the next-layer A fragment) and
// bias-via-C-operand MMAs (no accumulator-init MOVs).

#define TPB     256
#define LAYERS  5
#define WSTRIDE 40   // halves per W row (80 B): conflict-free LDS/LDSM

struct __align__(16) Smem {
    __half  W[LAYERS * 96 * WSTRIDE];  // rows 0-63 (r,z) pre-scaled by 0.5
    __half  FCW[32 * WSTRIDE];
    float   BRZ[LAYERS * 64];          // 0.5*(b_ih+b_hh): r units 0..31, z 32..63
    float   BNI[LAYERS * 32];          // b_ih (n gate)
    __half2 BNH2[LAYERS * 16];         // b_hh (n gate) as packed pairs
    float   FCB[32];
};

__device__ __forceinline__ uint32_t pack_h2(float lo, float hi) {
    uint32_t r;  // first src -> upper 16 bits
    asm("cvt.rn.f16x2.f32 %0, %1, %2;" : "=r"(r) : "f"(hi), "f"(lo));
    return r;
}
__device__ __forceinline__ uint32_t tanh2(uint32_t x) {
    uint32_t y; asm("tanh.approx.f16x2 %0, %1;" : "=r"(y) : "r"(x)); return y;
}
__device__ __forceinline__ uint32_t hfma2(uint32_t a, uint32_t b, uint32_t c) {
    uint32_t d; asm("fma.rn.f16x2 %0, %1, %2, %3;" : "=r"(d) : "r"(a), "r"(b), "r"(c));
    return d;
}
__device__ __forceinline__ uint32_t hmul2(uint32_t a, uint32_t b) {
    uint32_t d; asm("mul.rn.f16x2 %0, %1, %2;" : "=r"(d) : "r"(a), "r"(b));
    return d;
}
// accumulate in place: D += A*B
__device__ __forceinline__ void mma_acc(float* d, const uint32_t* a, const uint32_t* b) {
    asm volatile(
        "mma.sync.aligned.m16n8k16.row.col.f32.f16.f16.f32 "
        "{%0,%1,%2,%3}, {%4,%5,%6,%7}, {%8,%9}, {%0,%1,%2,%3};"
        : "+f"(d[0]), "+f"(d[1]), "+f"(d[2]), "+f"(d[3])
        : "r"(a[0]), "r"(a[1]), "r"(a[2]), "r"(a[3]), "r"(b[0]), "r"(b[1]));
}
// fresh D = A*B + {cx,cy,cx,cy}  (bias enters via C operand, no init MOVs)
__device__ __forceinline__ void mma_bias(float* d, const uint32_t* a, const uint32_t* b,
                                         float cx, float cy) {
    asm volatile(
        "mma.sync.aligned.m16n8k16.row.col.f32.f16.f16.f32 "
        "{%0,%1,%2,%3}, {%4,%5,%6,%7}, {%8,%9}, {%10,%11,%10,%11};"
        : "=f"(d[0]), "=f"(d[1]), "=f"(d[2]), "=f"(d[3])
        : "r"(a[0]), "r"(a[1]), "r"(a[2]), "r"(a[3]), "r"(b[0]), "r"(b[1]),
          "f"(cx), "f"(cy));
}
__device__ __forceinline__ void ldsm_x4(uint32_t* r, uint32_t saddr) {
    asm volatile("ldmatrix.sync.aligned.m8n8.x4.shared.b16 {%0,%1,%2,%3}, [%4];"
        : "=r"(r[0]), "=r"(r[1]), "=r"(r[2]), "=r"(r[3]) : "r"(saddr));
}

__global__ void __launch_bounds__(TPB, 2)
gru_hmma_kernel(const float* __restrict__ x,
                const float* __restrict__ w_ih,
                const float* __restrict__ b_ih,
                const float* __restrict__ b_hh,
                const float* __restrict__ fc_w,
                const float* __restrict__ fc_b,
                float* __restrict__ out)
{
    __shared__ Smem S;
    const int tid = threadIdx.x;

    // ---- stage weights (r/z rows scaled 0.5) + fused biases ----
    for (int i = tid; i < LAYERS * 96 * 32; i += TPB) {
        int l = i / 3072, row = (i % 3072) >> 5, k = i & 31;
        float scale = (row < 64) ? 0.5f : 1.0f;
        S.W[(l * 96 + row) * WSTRIDE + k] = __float2half(w_ih[i] * scale);
    }
    for (int i = tid; i < 32 * 32; i += TPB)
        S.FCW[(i >> 5) * WSTRIDE + (i & 31)] = __float2half(fc_w[i]);
    for (int i = tid; i < LAYERS * 96; i += TPB) {
        int l = i / 96, r = i % 96;
        float bi = b_ih[i], bh = b_hh[i];
        if (r < 64) S.BRZ[l * 64 + r] = 0.5f * (bi + bh);
        else        S.BNI[l * 32 + r - 64] = bi;
        (void)bh;
    }
    for (int i = tid; i < LAYERS * 16; i += TPB) {       // b_hh n-gate as half2
        int l = i / 16, p = i % 16;
        S.BNH2[i] = __floats2half2_rn(b_hh[l * 96 + 64 + 2 * p],
                                      b_hh[l * 96 + 64 + 2 * p + 1]);
    }
    for (int i = tid; i < 32; i += TPB) S.FCB[i] = fc_b[i];
    __syncthreads();

    const int warp = tid >> 5, lane = tid & 31;
    const int qrow = lane >> 2;          // fragment row within 8-row group
    const int c    = (lane & 3) * 2;     // fragment col pair base
    const size_t rowbase = (size_t)blockIdx.x * 256 + warp * 32;

    const uint32_t H05  = 0x38003800u;   // half2(+0.5, +0.5)
    const uint32_t HN05 = 0xB800B800u;   // half2(-0.5, -0.5)

    // per-thread ldmatrix address offset
    const uint32_t lm_off = (uint32_t)((lane & 7) * (WSTRIDE * 2)
                                       + ((lane >> 4) & 1) * 32
                                       + ((lane >> 3) & 1) * 16);
    const uint32_t wbase = (uint32_t)__cvta_generic_to_shared(S.W)   + lm_off;
    const uint32_t fbase = (uint32_t)__cvta_generic_to_shared(S.FCW) + lm_off;

    // ---- A fragments for layer 1 from gmem (fp32 -> f16x2) ----
    uint32_t A[2][2][4];
#pragma unroll
    for (int m = 0; m < 2; m++) {
        const size_t r0 = rowbase + m * 16 + qrow;
#pragma unroll
        for (int q = 0; q < 2; q++) {
            const float* p0 = x + r0 * 32 + q * 16 + c;
            const float* p1 = x + (r0 + 8) * 32 + q * 16 + c;
            float2 v00 = *(const float2*)p0;
            float2 v10 = *(const float2*)p1;
            float2 v01 = *(const float2*)(p0 + 8);
            float2 v11 = *(const float2*)(p1 + 8);
            A[m][q][0] = pack_h2(v00.x, v00.y);
            A[m][q][1] = pack_h2(v10.x, v10.y);
            A[m][q][2] = pack_h2(v01.x, v01.y);
            A[m][q][3] = pack_h2(v11.x, v11.y);
        }
    }

    // ---- 5 GRU layers ----
#pragma unroll
    for (int l = 0; l < LAYERS; l++) {
        uint32_t nA[2][2][4];
#pragma unroll
        for (int j = 0; j < 4; j++) {        // unit group: units j*8 + {c, c+1}
            uint32_t Br[4], Bz[4], Bn[4];
            const uint32_t la = wbase + (uint32_t)((l * 96 + j * 8) * (WSTRIDE * 2));
            ldsm_x4(Br, la);
            ldsm_x4(Bz, la + 32 * (WSTRIDE * 2));
            ldsm_x4(Bn, la + 64 * (WSTRIDE * 2));

            const float2 br = *(const float2*)&S.BRZ[l * 64      + j * 8 + c];
            const float2 bz = *(const float2*)&S.BRZ[l * 64 + 32 + j * 8 + c];
            const float2 bi = *(const float2*)&S.BNI[l * 32      + j * 8 + c];
            const uint32_t bh2 = *(const uint32_t*)&S.BNH2[l * 16 + j * 4 + (lane & 3)];
#pragma unroll
            for (int m = 0; m < 2; m++) {
                float Dr[4], Dz[4], Dn[4];
                mma_bias(Dr, A[m][0], Br + 0, br.x, br.y); mma_acc(Dr, A[m][1], Br + 2);
                mma_bias(Dz, A[m][0], Bz + 0, bz.x, bz.y); mma_acc(Dz, A[m][1], Bz + 2);
                mma_bias(Dn, A[m][0], Bn + 0, bi.x, bi.y); mma_acc(Dn, A[m][1], Bn + 2);
                // fp16x2 epilogue per row-pair p (cols c, c+1)
#pragma unroll
                for (int p = 0; p < 2; p++) {
                    uint32_t dr2 = pack_h2(Dr[2*p], Dr[2*p+1]);
                    uint32_t dz2 = pack_h2(Dz[2*p], Dz[2*p+1]);
                    uint32_t dn2 = pack_h2(Dn[2*p], Dn[2*p+1]);
                    uint32_t r2  = hfma2(tanh2(dr2), H05, H05);    // sigmoid
                    uint32_t zc2 = hfma2(tanh2(dz2), HN05, H05);   // 1 - z
                    uint32_t n2  = tanh2(hfma2(r2, bh2, dn2));
                    nA[m][j >> 1][(j & 1) * 2 + p] = hmul2(zc2, n2); // (1-z)*n
                }
            }
        }
#pragma unroll
        for (int m = 0; m < 2; m++)
#pragma unroll
            for (int q = 0; q < 2; q++)
#pragma unroll
                for (int e = 0; e < 4; e++) A[m][q][e] = nA[m][q][e];
    }

    // ---- FC: out = H @ fc_w^T + fc_b ----
#pragma unroll
    for (int jt = 0; jt < 4; jt++) {
        uint32_t Bf[4];
        ldsm_x4(Bf, fbase + (uint32_t)(jt * 8 * (WSTRIDE * 2)));
        const float2 fb = *(const float2*)&S.FCB[jt * 8 + c];
#pragma unroll
        for (int m = 0; m < 2; m++) {
            float D[4];
            mma_bias(D, A[m][0], Bf + 0, fb.x, fb.y);
            mma_acc(D, A[m][1], Bf + 2);
            const size_t r0 = rowbase + m * 16 + qrow;
            *(float2*)&out[r0 * 32       + jt * 8 + c] = make_float2(D[0], D[1]);
            *(float2*)&out[(r0 + 8) * 32 + jt * 8 + c] = make_float2(D[2], D[3]);
        }
    }
}

extern "C" void kernel_launch(void* const* d_in, const int* in_sizes, int n_in,
                              void* d_out, int out_size)
{
    const float* x    = (const float*)d_in[0];
    const float* w_ih = (const float*)d_in[1];
    // d_in[2] = w_hh : unused (SEQ=1, h0=0)
    const float* b_ih = (const float*)d_in[3];
    const float* b_hh = (const float*)d_in[4];
    const float* fc_w = (const float*)d_in[5];
    const float* fc_b = (const float*)d_in[6];
    float* out = (float*)d_out;

    const int batch = in_sizes[0] / 32;   // 1048576
    const int grid  = batch / 256;        // 256 rows per CTA (8 warps x 32)

    gru_hmma_kernel<<<grid, TPB>>>(x, w_ih, b_ih, b_hh, fc_w, fc_b, out);
}

// round 7
// speedup vs baseline: 7.1871x; 1.1499x over previous
#include <cuda_runtime.h>
#include <cuda_fp16.h>
#include <cstdint>

// GRU (SEQ=1, h0=0 => w_hh unused) via warp-level HMMA m16n8k16 fragment
// chaining. Round 7: one 16-row M-tile per warp (halved per-warp serial
// chain, lower reg pressure -> 3 CTAs/SM), 4 sequential tile-halves per CTA
// to amortize weight staging. Epilogue identical to round 6.

#define TPB     256
#define LAYERS  5
#define WSTRIDE 40    // halves per W row (80 B): conflict-free LDS/LDSM
#define NTILES  4     // 128-row halves per CTA -> CTA covers 512 rows

struct __align__(16) Smem {
    __half  W[LAYERS * 96 * WSTRIDE];  // rows 0-63 (r,z) pre-scaled by 0.5
    __half  FCW[32 * WSTRIDE];
    float   BRZ[LAYERS * 64];          // 0.5*(b_ih+b_hh): r units 0..31, z 32..63
    float   BNI[LAYERS * 32];          // b_ih (n gate)
    __half2 BNH2[LAYERS * 16];         // b_hh (n gate) packed pairs
    float   FCB[32];
};

__device__ __forceinline__ uint32_t pack_h2(float lo, float hi) {
    uint32_t r;  // first src -> upper 16 bits
    asm("cvt.rn.f16x2.f32 %0, %1, %2;" : "=r"(r) : "f"(hi), "f"(lo));
    return r;
}
__device__ __forceinline__ uint32_t tanh2(uint32_t x) {
    uint32_t y; asm("tanh.approx.f16x2 %0, %1;" : "=r"(y) : "r"(x)); return y;
}
__device__ __forceinline__ uint32_t hfma2(uint32_t a, uint32_t b, uint32_t c) {
    uint32_t d; asm("fma.rn.f16x2 %0, %1, %2, %3;" : "=r"(d) : "r"(a), "r"(b), "r"(c));
    return d;
}
__device__ __forceinline__ uint32_t hmul2(uint32_t a, uint32_t b) {
    uint32_t d; asm("mul.rn.f16x2 %0, %1, %2;" : "=r"(d) : "r"(a), "r"(b));
    return d;
}
__device__ __forceinline__ void mma_acc(float* d, const uint32_t* a, const uint32_t* b) {
    asm volatile(
        "mma.sync.aligned.m16n8k16.row.col.f32.f16.f16.f32 "
        "{%0,%1,%2,%3}, {%4,%5,%6,%7}, {%8,%9}, {%0,%1,%2,%3};"
        : "+f"(d[0]), "+f"(d[1]), "+f"(d[2]), "+f"(d[3])
        : "r"(a[0]), "r"(a[1]), "r"(a[2]), "r"(a[3]), "r"(b[0]), "r"(b[1]));
}
__device__ __forceinline__ void mma_bias(float* d, const uint32_t* a, const uint32_t* b,
                                         float cx, float cy) {
    asm volatile(
        "mma.sync.aligned.m16n8k16.row.col.f32.f16.f16.f32 "
        "{%0,%1,%2,%3}, {%4,%5,%6,%7}, {%8,%9}, {%10,%11,%10,%11};"
        : "=f"(d[0]), "=f"(d[1]), "=f"(d[2]), "=f"(d[3])
        : "r"(a[0]), "r"(a[1]), "r"(a[2]), "r"(a[3]), "r"(b[0]), "r"(b[1]),
          "f"(cx), "f"(cy));
}
__device__ __forceinline__ void ldsm_x4(uint32_t* r, uint32_t saddr) {
    asm volatile("ldmatrix.sync.aligned.m8n8.x4.shared.b16 {%0,%1,%2,%3}, [%4];"
        : "=r"(r[0]), "=r"(r[1]), "=r"(r[2]), "=r"(r[3]) : "r"(saddr));
}

__global__ void __launch_bounds__(TPB, 3)
gru_hmma_kernel(const float* __restrict__ x,
                const float* __restrict__ w_ih,
                const float* __restrict__ b_ih,
                const float* __restrict__ b_hh,
                const float* __restrict__ fc_w,
                const float* __restrict__ fc_b,
                float* __restrict__ out)
{
    __shared__ Smem S;
    const int tid = threadIdx.x;

    // ---- stage weights (r/z rows scaled 0.5) + fused biases ----
    for (int i = tid; i < LAYERS * 96 * 32; i += TPB) {
        int l = i / 3072, row = (i % 3072) >> 5, k = i & 31;
        float scale = (row < 64) ? 0.5f : 1.0f;
        S.W[(l * 96 + row) * WSTRIDE + k] = __float2half(w_ih[i] * scale);
    }
    for (int i = tid; i < 32 * 32; i += TPB)
        S.FCW[(i >> 5) * WSTRIDE + (i & 31)] = __float2half(fc_w[i]);
    for (int i = tid; i < LAYERS * 96; i += TPB) {
        int l = i / 96, r = i % 96;
        if (r < 64) S.BRZ[l * 64 + r] = 0.5f * (b_ih[i] + b_hh[i]);
        else        S.BNI[l * 32 + r - 64] = b_ih[i];
    }
    for (int i = tid; i < LAYERS * 16; i += TPB) {
        int l = i / 16, p = i % 16;
        S.BNH2[i] = __floats2half2_rn(b_hh[l * 96 + 64 + 2 * p],
                                      b_hh[l * 96 + 64 + 2 * p + 1]);
    }
    for (int i = tid; i < 32; i += TPB) S.FCB[i] = fc_b[i];
    __syncthreads();

    const int warp = tid >> 5, lane = tid & 31;
    const int qrow = lane >> 2;
    const int c    = (lane & 3) * 2;

    const uint32_t H05  = 0x38003800u;   // half2(+0.5)
    const uint32_t HN05 = 0xB800B800u;   // half2(-0.5)

    const uint32_t lm_off = (uint32_t)((lane & 7) * (WSTRIDE * 2)
                                       + ((lane >> 4) & 1) * 32
                                       + ((lane >> 3) & 1) * 16);
    const uint32_t wbase = (uint32_t)__cvta_generic_to_shared(S.W)   + lm_off;
    const uint32_t fbase = (uint32_t)__cvta_generic_to_shared(S.FCW) + lm_off;

#pragma unroll 1
    for (int it = 0; it < NTILES; it++) {
        const size_t rowbase = (size_t)blockIdx.x * (128 * NTILES) + it * 128 + warp * 16;
        const size_t r0 = rowbase + qrow;

        // ---- A fragments for layer 1 from gmem (fp32 -> f16x2) ----
        uint32_t A[2][4];
#pragma unroll
        for (int q = 0; q < 2; q++) {
            const float* p0 = x + r0 * 32 + q * 16 + c;
            const float* p1 = x + (r0 + 8) * 32 + q * 16 + c;
            float2 v00 = *(const float2*)p0;
            float2 v10 = *(const float2*)p1;
            float2 v01 = *(const float2*)(p0 + 8);
            float2 v11 = *(const float2*)(p1 + 8);
            A[q][0] = pack_h2(v00.x, v00.y);
            A[q][1] = pack_h2(v10.x, v10.y);
            A[q][2] = pack_h2(v01.x, v01.y);
            A[q][3] = pack_h2(v11.x, v11.y);
        }

        // ---- 5 GRU layers ----
#pragma unroll
        for (int l = 0; l < LAYERS; l++) {
            uint32_t nA[2][4];
#pragma unroll
            for (int j = 0; j < 4; j++) {
                uint32_t Br[4], Bz[4], Bn[4];
                const uint32_t la = wbase + (uint32_t)((l * 96 + j * 8) * (WSTRIDE * 2));
                ldsm_x4(Br, la);
                ldsm_x4(Bz, la + 32 * (WSTRIDE * 2));
                ldsm_x4(Bn, la + 64 * (WSTRIDE * 2));

                const float2 br = *(const float2*)&S.BRZ[l * 64      + j * 8 + c];
                const float2 bz = *(const float2*)&S.BRZ[l * 64 + 32 + j * 8 + c];
                const float2 bi = *(const float2*)&S.BNI[l * 32      + j * 8 + c];
                const uint32_t bh2 = *(const uint32_t*)&S.BNH2[l * 16 + j * 4 + (lane & 3)];

                float Dr[4], Dz[4], Dn[4];
                mma_bias(Dr, A[0], Br + 0, br.x, br.y); mma_acc(Dr, A[1], Br + 2);
                mma_bias(Dz, A[0], Bz + 0, bz.x, bz.y); mma_acc(Dz, A[1], Bz + 2);
                mma_bias(Dn, A[0], Bn + 0, bi.x, bi.y); mma_acc(Dn, A[1], Bn + 2);
#pragma unroll
                for (int p = 0; p < 2; p++) {
                    uint32_t dr2 = pack_h2(Dr[2*p], Dr[2*p+1]);
                    uint32_t dz2 = pack_h2(Dz[2*p], Dz[2*p+1]);
                    uint32_t dn2 = pack_h2(Dn[2*p], Dn[2*p+1]);
                    uint32_t r2  = hfma2(tanh2(dr2), H05, H05);     // sigmoid
                    uint32_t zc2 = hfma2(tanh2(dz2), HN05, H05);    // 1 - z
                    uint32_t n2  = tanh2(hfma2(r2, bh2, dn2));
                    nA[j >> 1][(j & 1) * 2 + p] = hmul2(zc2, n2);   // (1-z)*n
                }
            }
#pragma unroll
            for (int q = 0; q < 2; q++)
#pragma unroll
                for (int e = 0; e < 4; e++) A[q][e] = nA[q][e];
        }

        // ---- FC: out = H @ fc_w^T + fc_b ----
#pragma unroll
        for (int jt = 0; jt < 4; jt++) {
            uint32_t Bf[4];
            ldsm_x4(Bf, fbase + (uint32_t)(jt * 8 * (WSTRIDE * 2)));
            const float2 fb = *(const float2*)&S.FCB[jt * 8 + c];
            float D[4];
            mma_bias(D, A[0], Bf + 0, fb.x, fb.y);
            mma_acc(D, A[1], Bf + 2);
            *(float2*)&out[r0 * 32       + jt * 8 + c] = make_float2(D[0], D[1]);
            *(float2*)&out[(r0 + 8) * 32 + jt * 8 + c] = make_float2(D[2], D[3]);
        }
    }
}

extern "C" void kernel_launch(void* const* d_in, const int* in_sizes, int n_in,
                              void* d_out, int out_size)
{
    const float* x    = (const float*)d_in[0];
    const float* w_ih = (const float*)d_in[1];
    // d_in[2] = w_hh : unused (SEQ=1, h0=0)
    const float* b_ih = (const float*)d_in[3];
    const float* b_hh = (const float*)d_in[4];
    const float* fc_w = (const float*)d_in[5];
    const float* fc_b = (const float*)d_in[6];
    float* out = (float*)d_out;

    const int batch = in_sizes[0] / 32;        // 1048576
    const int grid  = batch / (128 * NTILES);  // 2048

    gru_hmma_kernel<<<grid, TPB>>>(x, w_ih, b_ih, b_hh, fc_w, fc_b, out);
}